// round 4
// baseline (speedup 1.0000x reference)
#include <cuda_runtime.h>
#include <cuda_bf16.h>
#include <math.h>

// ---------------- problem constants ----------------
#define BATCH        256
#define EMBED_DIM    512
#define NUM_CLASSES  100000
#define NUM_SUB      3
#define SCALE        64.0f
// margin = 0.5
#define COS_M  0.8775825618903728f
#define SIN_M  0.479425538604203f
#define TH_    (-0.8775825618903728f)
#define MM_    0.2397127693021015f

// GEMM tiling
#define CPS    32          // classes per subtile (32 weight rows per subcenter pass)
#define SUBT   5           // subtiles per CTA
#define GRID2  625         // 625 * 5 * 32 = 100000 classes exactly
#define WS_STRIDE 33       // w_s row-dim padded stride
#define ES_STRIDE 516      // e_s k-dim padded stride (floats), 16B aligned
#define CM_STRIDE 33       // cm class-dim padded stride

// ---------------- scratch (device globals; no allocation) ----------------
__device__ float4 g_enorm4[BATCH * (EMBED_DIM / 4)];   // normalized embeddings
__device__ float  g_part[GRID2 * BATCH];               // per-(CTA,sample) partial sums
__device__ float  g_labcos[BATCH];                     // label-class cosine (max over 3 subcenters)

// ---------------- K1: normalize embeddings ----------------
__global__ void k1_normalize(const float* __restrict__ emb) {
    int n = blockIdx.x;
    int tid = threadIdx.x;             // 128
    const float4* row = (const float4*)(emb + (size_t)n * EMBED_DIM);
    float4 v = row[tid];
    float ss = v.x * v.x + v.y * v.y + v.z * v.z + v.w * v.w;

    __shared__ float red[128];
    red[tid] = ss;
    __syncthreads();
    for (int o = 64; o > 0; o >>= 1) {
        if (tid < o) red[tid] += red[tid + o];
        __syncthreads();
    }
    float rn = 1.0f / fmaxf(sqrtf(red[0]), 1e-12f);
    g_enorm4[n * (EMBED_DIM / 4) + tid] = make_float4(v.x * rn, v.y * rn, v.z * rn, v.w * rn);
}

// ---------------- KL: label-class cosine (3 subcenters, take max) ----------------
// labels are int32 (JAX without x64 downcasts jnp.int64 -> int32).
// 256 blocks (one per sample), 96 threads = 3 warps, warp s handles subcenter s.
__global__ void kl_label(const float* __restrict__ weight,
                         const int* __restrict__ labels) {
    int n = blockIdx.x;
    int wid = threadIdx.x >> 5;        // 0..2
    int lane = threadIdx.x & 31;
    int lab = labels[n];
    if (lab < 0) lab = 0;                       // defensive clamp: a dtype
    if (lab >= NUM_CLASSES) lab = NUM_CLASSES - 1;  // mistake shows as rel_err, not IMA

    const float4* er = g_enorm4 + n * (EMBED_DIM / 4);
    const float4* wr = (const float4*)(weight + (size_t)(lab * NUM_SUB + wid) * EMBED_DIM);

    float d = 0.0f, q = 0.0f;
    #pragma unroll
    for (int j = 0; j < 4; j++) {
        float4 e = er[lane + 32 * j];
        float4 w = wr[lane + 32 * j];
        d += e.x * w.x + e.y * w.y + e.z * w.z + e.w * w.w;
        q += w.x * w.x + w.y * w.y + w.z * w.z + w.w * w.w;
    }
    #pragma unroll
    for (int o = 16; o > 0; o >>= 1) {
        d += __shfl_xor_sync(0xFFFFFFFFu, d, o);
        q += __shfl_xor_sync(0xFFFFFFFFu, q, o);
    }
    __shared__ float sc[3];
    if (lane == 0) sc[wid] = d / fmaxf(sqrtf(q), 1e-12f);
    __syncthreads();
    if (threadIdx.x == 0) g_labcos[n] = fmaxf(sc[0], fmaxf(sc[1], sc[2]));
}

// ---------------- K2: fused cosine GEMM + subcenter-max + exp-sum ----------------
// CTA owns 160 classes (5 subtiles x 32). For each subtile, 3 subcenter passes:
// pass s loads weight rows (c0+r)*3+s (each weight row read once from DRAM overall),
// computes the 256x32 cosine block, and fmax-merges into cm[sample][class].
// After the 3 passes: per-sample sum of exp(64*cosmax - 64) accumulated into a
// per-thread register (thread tid owns sample tid). Fixed shift is exact:
// logits = 64*cos <= 64 always, so exp(logit-64) never overflows and the
// dominant terms (~e^-50) are comfortably inside fp32 normal range.
__global__ void __launch_bounds__(256, 1)
k2_fused(const float* __restrict__ weight) {
    extern __shared__ float smem[];
    float* w_s = smem;                              // [512][33]       16896 floats
    float* e_s = w_s + EMBED_DIM * WS_STRIDE;       // [32][516]       16512 floats
    float* rn  = e_s + 32 * ES_STRIDE;              // [32]
    float* cm  = rn + 32;                           // [256][33]        8448 floats

    int tid  = threadIdx.x;
    int wid  = tid >> 5;
    int lane = tid & 31;

    float psum = 0.0f;    // partial exp-sum for sample 'tid'

    for (int t = 0; t < SUBT; t++) {
        int c0 = blockIdx.x * (SUBT * CPS) + t * CPS;

        for (int s = 0; s < NUM_SUB; s++) {
            // ---- weight tile: warp wid loads rows r = wid*4..wid*4+3 (global row (c0+r)*3+s) ----
            for (int rr = 0; rr < 4; rr++) {
                int r = wid * 4 + rr;
                const float4* wrow =
                    (const float4*)(weight + (size_t)((c0 + r) * NUM_SUB + s) * EMBED_DIM);
                float ss = 0.0f;
                #pragma unroll
                for (int j = 0; j < 4; j++) {
                    float4 v = wrow[lane + 32 * j];
                    int k = (lane + 32 * j) * 4;
                    w_s[(k + 0) * WS_STRIDE + r] = v.x;
                    w_s[(k + 1) * WS_STRIDE + r] = v.y;
                    w_s[(k + 2) * WS_STRIDE + r] = v.z;
                    w_s[(k + 3) * WS_STRIDE + r] = v.w;
                    ss += v.x * v.x + v.y * v.y + v.z * v.z + v.w * v.w;
                }
                #pragma unroll
                for (int o = 16; o > 0; o >>= 1) ss += __shfl_xor_sync(0xFFFFFFFFu, ss, o);
                if (lane == 0) rn[r] = 1.0f / fmaxf(sqrtf(ss), 1e-12f);
            }
            __syncthreads();
            float my_rn = rn[lane];

            // ---- 8 passes of 32 embeddings ----
            for (int eb = 0; eb < 8; eb++) {
                const float4* e4 = g_enorm4 + eb * 32 * (EMBED_DIM / 4);
                for (int i = tid; i < 32 * (EMBED_DIM / 4); i += 256) {
                    float4 v = e4[i];
                    *((float4*)&e_s[(i >> 7) * ES_STRIDE + (i & 127) * 4]) = v;
                }
                __syncthreads();

                int n0 = wid * 4;
                float a0 = 0.f, a1 = 0.f, a2 = 0.f, a3 = 0.f;
                #pragma unroll 8
                for (int k = 0; k < EMBED_DIM; k += 4) {
                    float w0 = w_s[(k + 0) * WS_STRIDE + lane];
                    float w1 = w_s[(k + 1) * WS_STRIDE + lane];
                    float w2 = w_s[(k + 2) * WS_STRIDE + lane];
                    float w3 = w_s[(k + 3) * WS_STRIDE + lane];
                    float4 eA = *((const float4*)&e_s[(n0 + 0) * ES_STRIDE + k]);
                    float4 eB = *((const float4*)&e_s[(n0 + 1) * ES_STRIDE + k]);
                    float4 eC = *((const float4*)&e_s[(n0 + 2) * ES_STRIDE + k]);
                    float4 eD = *((const float4*)&e_s[(n0 + 3) * ES_STRIDE + k]);
                    a0 += w0 * eA.x + w1 * eA.y + w2 * eA.z + w3 * eA.w;
                    a1 += w0 * eB.x + w1 * eB.y + w2 * eB.z + w3 * eB.w;
                    a2 += w0 * eC.x + w1 * eC.y + w2 * eC.z + w3 * eC.w;
                    a3 += w0 * eD.x + w1 * eD.y + w2 * eD.z + w3 * eD.w;
                }

                int sm0 = eb * 32 + n0;     // first of this warp's 4 samples
                float v0 = a0 * my_rn, v1 = a1 * my_rn, v2 = a2 * my_rn, v3 = a3 * my_rn;
                if (s == 0) {
                    cm[(sm0 + 0) * CM_STRIDE + lane] = v0;
                    cm[(sm0 + 1) * CM_STRIDE + lane] = v1;
                    cm[(sm0 + 2) * CM_STRIDE + lane] = v2;
                    cm[(sm0 + 3) * CM_STRIDE + lane] = v3;
                } else {
                    cm[(sm0 + 0) * CM_STRIDE + lane] = fmaxf(cm[(sm0 + 0) * CM_STRIDE + lane], v0);
                    cm[(sm0 + 1) * CM_STRIDE + lane] = fmaxf(cm[(sm0 + 1) * CM_STRIDE + lane], v1);
                    cm[(sm0 + 2) * CM_STRIDE + lane] = fmaxf(cm[(sm0 + 2) * CM_STRIDE + lane], v2);
                    cm[(sm0 + 3) * CM_STRIDE + lane] = fmaxf(cm[(sm0 + 3) * CM_STRIDE + lane], v3);
                }
                __syncthreads();   // cm visible; e_s safe to overwrite next eb
            }
        }

        // ---- merge: thread tid owns sample tid; sum exp(64*cosmax - 64) over 32 classes ----
        float acc = 0.0f;
        #pragma unroll 4
        for (int c = 0; c < CPS; c++)
            acc += __expf(SCALE * cm[tid * CM_STRIDE + c] - 64.0f);
        psum += acc;
        __syncthreads();   // all merge reads done before next subtile overwrites cm/w_s
    }

    g_part[blockIdx.x * BATCH + tid] = psum;
}

// ---------------- K3: final reduce + label margin correction + mean ----------------
// Single block, 256 threads; thread n handles sample n; then tree-reduce the mean.
__global__ void k3_final(float* __restrict__ out) {
    int tid = threadIdx.x;

    float tot = 0.0f;
    for (int c = 0; c < GRID2; c++)
        tot += g_part[c * BATCH + tid];          // coalesced across threads

    float cl = g_labcos[tid];
    float sine = sqrtf(fminf(fmaxf(1.0f - cl * cl, 0.0f), 1.0f));
    float phi = cl * COS_M - sine * SIN_M;
    phi = (cl > TH_) ? phi : (cl - MM_);

    // replace label's plain-cos term with the margined term (shared shift of 64)
    float t2 = tot - __expf(SCALE * cl - 64.0f) + __expf(SCALE * phi - 64.0f);
    float loss = 64.0f + logf(t2) - SCALE * phi;   // logz - label_logit

    __shared__ float red[256];
    red[tid] = loss;
    __syncthreads();
    for (int o = 128; o > 0; o >>= 1) {
        if (tid < o) red[tid] += red[tid + o];
        __syncthreads();
    }
    if (tid == 0) out[0] = red[0] * (1.0f / BATCH);
}

// ---------------- launch ----------------
extern "C" void kernel_launch(void* const* d_in, const int* in_sizes, int n_in,
                              void* d_out, int out_size) {
    const float* emb    = (const float*)d_in[0];
    const int*   labels = (const int*)d_in[1];       // int32! (JAX x64 disabled)
    const float* weight = (const float*)d_in[2];
    float* out = (float*)d_out;

    k1_normalize<<<BATCH, 128>>>(emb);
    kl_label<<<BATCH, 96>>>(weight, labels);

    size_t smem_bytes = (size_t)(EMBED_DIM * WS_STRIDE + 32 * ES_STRIDE + 32
                                 + BATCH * CM_STRIDE) * sizeof(float);   // 167552 B
    cudaFuncSetAttribute(k2_fused, cudaFuncAttributeMaxDynamicSharedMemorySize,
                         (int)smem_bytes);
    k2_fused<<<GRID2, 256, smem_bytes>>>(weight);

    k3_final<<<1, 256>>>(out);
}

// round 9
// speedup vs baseline: 11.2500x; 11.2500x over previous
#include <cuda_runtime.h>
#include <cuda_bf16.h>
#include <math.h>
#include <stdint.h>

// ---------------- problem constants ----------------
#define BATCH        256
#define EMBED_DIM    512
#define NUM_CLASSES  100000
#define NUM_SUB      3
#define NROWS        300000
#define SCALE        64.0f
#define COS_M  0.8775825618903728f
#define SIN_M  0.479425538604203f
#define TH_    (-0.8775825618903728f)
#define MM_    0.2397127693021015f

// ---------------- GEMM tiling (HMMA mma.sync path) ----------------
#define NT      48             // weight rows per CTA = 16 classes exactly
#define NCTA    6250           // 6250 * 48 = 300000
#define KCH     64             // k elems per chunk (128 B of bf16 per row)
#define NCHUNK  8

// smem offsets
#define SM_A    0              // 256 rows x 128B = 32768 (SW128 swizzled bf16)
#define SM_B    32768          // 48 rows x 128B = 6144
#define SM_RS   50176          // 48 floats (row sumsq -> rnorm)
#define CM_STRIDE 49           // cm[256][49] floats aliases [0, 50176)
#define SMEM_REQ 50432

// ---------------- device scratch (no allocation) ----------------
__device__ __align__(16) unsigned char g_embf[NCHUNK * 32768]; // swizzled bf16 emb, chunked
__device__ float4 g_enorm4[BATCH * (EMBED_DIM / 4)];
__device__ float  g_part[(size_t)NCTA * BATCH];
__device__ float  g_labcos[BATCH];
__device__ float  g_sums[BATCH];

// ---------------- helpers ----------------
__device__ __forceinline__ uint32_t s2u(const void* p) {
    uint32_t a;
    asm("{ .reg .u64 t; cvta.to.shared.u64 t, %1; cvt.u32.u64 %0, t; }" : "=r"(a) : "l"(p));
    return a;
}
#define LDM_X4(r, addr) \
    asm volatile("ldmatrix.sync.aligned.m8n8.x4.shared.b16 {%0,%1,%2,%3}, [%4];" \
        : "=r"((r)[0]), "=r"((r)[1]), "=r"((r)[2]), "=r"((r)[3]) : "r"(addr))

__device__ __forceinline__ void mma16816(float* d, const uint32_t* a, uint32_t b0, uint32_t b1) {
    asm volatile(
        "mma.sync.aligned.m16n8k16.row.col.f32.bf16.bf16.f32 "
        "{%0,%1,%2,%3}, {%4,%5,%6,%7}, {%8,%9}, {%0,%1,%2,%3};"
        : "+f"(d[0]), "+f"(d[1]), "+f"(d[2]), "+f"(d[3])
        : "r"(a[0]), "r"(a[1]), "r"(a[2]), "r"(a[3]), "r"(b0), "r"(b1));
}

// ---------------- K1: normalize; write fp32 + swizzled bf16 chunked layout ----------------
__global__ void k1_normalize(const float* __restrict__ emb) {
    int n = blockIdx.x;
    int t = threadIdx.x;   // 128
    float4 v = ((const float4*)(emb + (size_t)n * EMBED_DIM))[t];
    float ss = v.x * v.x + v.y * v.y + v.z * v.z + v.w * v.w;

    __shared__ float red[128];
    red[t] = ss;
    __syncthreads();
    for (int o = 64; o > 0; o >>= 1) { if (t < o) red[t] += red[t + o]; __syncthreads(); }
    float rn = 1.0f / fmaxf(sqrtf(red[0]), 1e-12f);

    float4 o4 = make_float4(v.x * rn, v.y * rn, v.z * rn, v.w * rn);
    g_enorm4[n * (EMBED_DIM / 4) + t] = o4;

    __nv_bfloat162 p0 = __floats2bfloat162_rn(o4.x, o4.y);
    __nv_bfloat162 p1 = __floats2bfloat162_rn(o4.z, o4.w);
    uint2 u;
    u.x = *(uint32_t*)&p0;
    u.y = *(uint32_t*)&p1;
    int chunk = t >> 4;                                // elem t*4 -> chunk (t*4)/64
    uint32_t boff = (uint32_t)n * 128 + (t & 15) * 8;
    uint32_t sw = boff ^ ((boff >> 3) & 0x70);
    *(uint2*)(g_embf + chunk * 32768 + sw) = u;
}

// ---------------- KL: exact fp32 label cosine ----------------
__global__ void kl_label(const float* __restrict__ weight, const int* __restrict__ labels) {
    int n = blockIdx.x;
    int wid = threadIdx.x >> 5;   // 0..2 (subcenter)
    int lane = threadIdx.x & 31;
    int lab = labels[n];
    if (lab < 0) lab = 0;
    if (lab >= NUM_CLASSES) lab = NUM_CLASSES - 1;

    const float4* er = g_enorm4 + n * (EMBED_DIM / 4);
    const float4* wr = (const float4*)(weight + (size_t)(lab * NUM_SUB + wid) * EMBED_DIM);
    float d = 0.0f, q = 0.0f;
    #pragma unroll
    for (int j = 0; j < 4; j++) {
        float4 e = er[lane + 32 * j];
        float4 w = wr[lane + 32 * j];
        d += e.x * w.x + e.y * w.y + e.z * w.z + e.w * w.w;
        q += w.x * w.x + w.y * w.y + w.z * w.z + w.w * w.w;
    }
    #pragma unroll
    for (int o = 16; o > 0; o >>= 1) {
        d += __shfl_xor_sync(0xFFFFFFFFu, d, o);
        q += __shfl_xor_sync(0xFFFFFFFFu, q, o);
    }
    __shared__ float sc[3];
    if (lane == 0) sc[wid] = d / fmaxf(sqrtf(q), 1e-12f);
    __syncthreads();
    if (threadIdx.x == 0) g_labcos[n] = fmaxf(sc[0], fmaxf(sc[1], sc[2]));
}

// ---------------- K2: bf16 HMMA GEMM + fused subcenter-max / exp epilogue ----------------
// CTA: 256 threads = 8 warps. M=256 (warp w -> samples w*32..w*32+31), N=48, K chunks of 64.
__global__ void __launch_bounds__(256, 2) k2_hmma(const float* __restrict__ weight) {
    extern __shared__ char sm[];
    uint32_t sb = s2u(sm);
    int tid = threadIdx.x;
    int w = tid >> 5;
    int lane = tid & 31;
    float* rsum = (float*)(sm + SM_RS);
    size_t wbase = (size_t)blockIdx.x * NT;

    if (tid < NT) rsum[tid] = 0.0f;

    float acc[2][6][4];
    #pragma unroll
    for (int mt = 0; mt < 2; mt++)
        #pragma unroll
        for (int nt = 0; nt < 6; nt++)
            #pragma unroll
            for (int i = 0; i < 4; i++) acc[mt][nt][i] = 0.0f;

    // --- ldmatrix lane address precompute ---
    // A 16x16 tile (mt, ks): mats (m0-7,klo)(m8-15,klo)(m0-7,khi)(m8-15,khi)
    int a_r0 = w * 32 + (lane & 7) + ((lane >> 3) & 1) * 8;
    uint32_t a_hi16 = ((lane >> 4) & 1) * 16;
    uint32_t xrA = (uint32_t)((a_r0 & 7) << 4);
    uint32_t aRow0 = sb + SM_A + a_r0 * 128;
    uint32_t aRow1 = aRow0 + 16 * 128;
    // B x4 group g covers n-tiles 2g,2g+1: mats (n0-7,klo)(n0-7,khi)(n8-15,klo)(n8-15,khi)
    int b_r0 = (lane & 7) + ((lane >> 4) & 1) * 8;
    uint32_t b_k16 = ((lane >> 3) & 1) * 16;
    uint32_t xrB = (uint32_t)((b_r0 & 7) << 4);
    uint32_t bRow0 = sb + SM_B + b_r0 * 128;

    // --- B-load thread mapping: threads 0..191, 4 threads per row ---
    int br = tid >> 2;
    int bq = tid & 3;

    __syncthreads();   // rsum init visible

    for (int kc = 0; kc < NCHUNK; kc++) {
        if (kc) __syncthreads();   // previous chunk's ldmatrix reads done

        // A chunk: straight copy of pre-swizzled bf16 (L2-resident)
        {
            const uint4* src = (const uint4*)(g_embf + kc * 32768);
            uint4* dst = (uint4*)(sm + SM_A);
            #pragma unroll
            for (int i = 0; i < 8; i++) dst[tid + 256 * i] = src[tid + 256 * i];
        }

        // B chunk: fp32 -> bf16 convert + SW128 swizzle + sumsq
        if (tid < 4 * NT) {
            const float4* wrow = (const float4*)(weight + (wbase + br) * EMBED_DIM + kc * KCH);
            float ss = 0.0f;
            #pragma unroll
            for (int s = 0; s < 4; s++) {
                int f = s * 4 + bq;                 // float4 index 0..15 (64B coalesced)
                float4 v = wrow[f];
                ss += v.x * v.x + v.y * v.y + v.z * v.z + v.w * v.w;
                __nv_bfloat162 p0 = __floats2bfloat162_rn(v.x, v.y);
                __nv_bfloat162 p1 = __floats2bfloat162_rn(v.z, v.w);
                uint2 u;
                u.x = *(uint32_t*)&p0;
                u.y = *(uint32_t*)&p1;
                uint32_t kb = (uint32_t)f * 8;
                *(uint2*)(sm + SM_B + br * 128 + (kb ^ ((br & 7) << 4))) = u;
            }
            ss += __shfl_xor_sync(0xFFFFFFFFu, ss, 1);
            ss += __shfl_xor_sync(0xFFFFFFFFu, ss, 2);
            if (bq == 0) rsum[br] += ss;
        }
        __syncthreads();

        // MMA: 4 k-steps x (2 m-tiles x 6 n-tiles)
        #pragma unroll
        for (int ks = 0; ks < 4; ks++) {
            uint32_t kbA = ((uint32_t)(ks * 32) + a_hi16) ^ xrA;
            uint32_t kbB = ((uint32_t)(ks * 32) + b_k16) ^ xrB;
            uint32_t a0[4], a1[4], bf[3][4];
            LDM_X4(a0, aRow0 + kbA);
            LDM_X4(a1, aRow1 + kbA);
            LDM_X4(bf[0], bRow0 + kbB);
            LDM_X4(bf[1], bRow0 + 16 * 128 + kbB);
            LDM_X4(bf[2], bRow0 + 32 * 128 + kbB);
            #pragma unroll
            for (int nt = 0; nt < 6; nt++) {
                uint32_t b0 = bf[nt >> 1][(nt & 1) * 2];
                uint32_t b1 = bf[nt >> 1][(nt & 1) * 2 + 1];
                mma16816(acc[0][nt], a0, b0, b1);
                mma16816(acc[1][nt], a1, b0, b1);
            }
        }
    }
    __syncthreads();   // all ldmatrix reads done before cm overwrites A region

    // finalize row rnorms
    if (tid < NT) rsum[tid] = 1.0f / fmaxf(sqrtf(rsum[tid]), 1e-12f);

    // dump accumulators to cm[256][49]
    float* cm = (float*)sm;
    int mrow = w * 32 + (lane >> 2);
    int mcol = (lane & 3) * 2;
    #pragma unroll
    for (int mt = 0; mt < 2; mt++) {
        #pragma unroll
        for (int nt = 0; nt < 6; nt++) {
            int m = mrow + mt * 16;
            int n = nt * 8 + mcol;
            cm[m * CM_STRIDE + n]           = acc[mt][nt][0];
            cm[m * CM_STRIDE + n + 1]       = acc[mt][nt][1];
            cm[(m + 8) * CM_STRIDE + n]     = acc[mt][nt][2];
            cm[(m + 8) * CM_STRIDE + n + 1] = acc[mt][nt][3];
        }
    }
    __syncthreads();

    // thread tid = sample tid: 16 classes, subcenter-max, exp-sum
    float psum = 0.0f;
    const float* myrow = cm + tid * CM_STRIDE;
    #pragma unroll 4
    for (int c = 0; c < NT / 3; c++) {
        float c0 = myrow[3 * c + 0] * rsum[3 * c + 0];
        float c1 = myrow[3 * c + 1] * rsum[3 * c + 1];
        float c2 = myrow[3 * c + 2] * rsum[3 * c + 2];
        float m = fmaxf(c0, fmaxf(c1, c2));
        psum += __expf(SCALE * m - 64.0f);
    }
    g_part[(size_t)blockIdx.x * BATCH + tid] = psum;
}

// ---------------- K3a: per-sample partial reduce (deterministic) ----------------
__global__ void k3a_reduce() {
    int n = blockIdx.x;
    int t = threadIdx.x;   // 256
    float s = 0.0f;
    for (int c = t; c < NCTA; c += 256) s += g_part[(size_t)c * BATCH + n];
    __shared__ float red[256];
    red[t] = s;
    __syncthreads();
    for (int o = 128; o > 0; o >>= 1) { if (t < o) red[t] += red[t + o]; __syncthreads(); }
    if (t == 0) g_sums[n] = red[0];
}

// ---------------- K3b: margin correction + loss + mean ----------------
__global__ void k3b_final(float* __restrict__ out) {
    int tid = threadIdx.x;   // 256
    float tot = g_sums[tid];
    float cl = g_labcos[tid];
    float sine = sqrtf(fminf(fmaxf(1.0f - cl * cl, 0.0f), 1.0f));
    float phi = cl * COS_M - sine * SIN_M;
    phi = (cl > TH_) ? phi : (cl - MM_);
    float t2 = tot - __expf(SCALE * cl - 64.0f) + __expf(SCALE * phi - 64.0f);
    float loss = 64.0f + logf(t2) - SCALE * phi;

    __shared__ float red[256];
    red[tid] = loss;
    __syncthreads();
    for (int o = 128; o > 0; o >>= 1) { if (tid < o) red[tid] += red[tid + o]; __syncthreads(); }
    if (tid == 0) out[0] = red[0] * (1.0f / BATCH);
}

// ---------------- launch ----------------
extern "C" void kernel_launch(void* const* d_in, const int* in_sizes, int n_in,
                              void* d_out, int out_size) {
    const float* emb    = (const float*)d_in[0];
    const int*   labels = (const int*)d_in[1];     // int32 (JAX x64 disabled)
    const float* weight = (const float*)d_in[2];
    float* out = (float*)d_out;

    k1_normalize<<<BATCH, 128>>>(emb);
    kl_label<<<BATCH, 96>>>(weight, labels);

    cudaFuncSetAttribute(k2_hmma, cudaFuncAttributeMaxDynamicSharedMemorySize, SMEM_REQ);
    k2_hmma<<<NCTA, 256, SMEM_REQ>>>(weight);

    k3a_reduce<<<BATCH, 256>>>();
    k3b_final<<<1, 256>>>(out);
}

// round 11
// speedup vs baseline: 13.8151x; 1.2280x over previous
#include <cuda_runtime.h>
#include <cuda_bf16.h>
#include <math.h>
#include <stdint.h>

// ---------------- problem constants ----------------
#define BATCH        256
#define EMBED_DIM    512
#define NUM_CLASSES  100000
#define NUM_SUB      3
#define NROWS        300000
#define SCALE        64.0f
#define COS_M  0.8775825618903728f
#define SIN_M  0.479425538604203f
#define TH_    (-0.8775825618903728f)
#define MM_    0.2397127693021015f

// ---------------- GEMM tiling ----------------
#define NT      96             // weight rows per CTA = 32 classes exactly
#define NCTA    3125           // 3125 * 96 = 300000
#define KCH     64             // k elems per chunk (128 B bf16 per row)
#define NCHUNK  8

// smem offsets
#define SM_A0   0              // 32768 (A chunk buf0, SW128 bf16)
#define SM_A1   32768          // 32768 (A chunk buf1)
#define SM_B0   65536          // 12288 (B buf0: 96 x 128B)
#define SM_B1   77824          // 12288 (B buf1)
#define CM_STRIDE 97           // cm[256][97] floats, aliases [0, 99328)
#define SM_RS   99328          // 96 floats
#define SMEM_REQ 99840

// ---------------- device scratch (no allocation) ----------------
__device__ __align__(16) unsigned char g_embf[NCHUNK * 32768]; // swizzled bf16 emb, chunked
__device__ float4 g_enorm4[BATCH * (EMBED_DIM / 4)];
__device__ float  g_part[(size_t)NCTA * BATCH];
__device__ float  g_labcos[BATCH];
__device__ float  g_sums[BATCH];

// ---------------- helpers ----------------
__device__ __forceinline__ uint32_t s2u(const void* p) {
    uint32_t a;
    asm("{ .reg .u64 t; cvta.to.shared.u64 t, %1; cvt.u32.u64 %0, t; }" : "=r"(a) : "l"(p));
    return a;
}
#define LDM_X4(r, addr) \
    asm volatile("ldmatrix.sync.aligned.m8n8.x4.shared.b16 {%0,%1,%2,%3}, [%4];" \
        : "=r"((r)[0]), "=r"((r)[1]), "=r"((r)[2]), "=r"((r)[3]) : "r"(addr))

__device__ __forceinline__ void mma16816(float* d, const uint32_t* a, uint32_t b0, uint32_t b1) {
    asm volatile(
        "mma.sync.aligned.m16n8k16.row.col.f32.bf16.bf16.f32 "
        "{%0,%1,%2,%3}, {%4,%5,%6,%7}, {%8,%9}, {%0,%1,%2,%3};"
        : "+f"(d[0]), "+f"(d[1]), "+f"(d[2]), "+f"(d[3])
        : "r"(a[0]), "r"(a[1]), "r"(a[2]), "r"(a[3]), "r"(b0), "r"(b1));
}
#define CP_ASYNC16(smaddr, gptr) \
    asm volatile("cp.async.ca.shared.global [%0], [%1], 16;" :: "r"(smaddr), "l"(gptr) : "memory")
#define CP_COMMIT()  asm volatile("cp.async.commit_group;" ::: "memory")
#define CP_WAIT0()   asm volatile("cp.async.wait_group 0;" ::: "memory")

// ---------------- K1: normalize; write fp32 + swizzled bf16 chunked layout ----------------
__global__ void k1_normalize(const float* __restrict__ emb) {
    int n = blockIdx.x;
    int t = threadIdx.x;   // 128
    float4 v = ((const float4*)(emb + (size_t)n * EMBED_DIM))[t];
    float ss = v.x * v.x + v.y * v.y + v.z * v.z + v.w * v.w;

    __shared__ float red[128];
    red[t] = ss;
    __syncthreads();
    for (int o = 64; o > 0; o >>= 1) { if (t < o) red[t] += red[t + o]; __syncthreads(); }
    float rn = 1.0f / fmaxf(sqrtf(red[0]), 1e-12f);

    float4 o4 = make_float4(v.x * rn, v.y * rn, v.z * rn, v.w * rn);
    g_enorm4[n * (EMBED_DIM / 4) + t] = o4;

    __nv_bfloat162 p0 = __floats2bfloat162_rn(o4.x, o4.y);
    __nv_bfloat162 p1 = __floats2bfloat162_rn(o4.z, o4.w);
    uint2 u;
    u.x = *(uint32_t*)&p0;
    u.y = *(uint32_t*)&p1;
    int chunk = t >> 4;
    uint32_t boff = (uint32_t)n * 128 + (t & 15) * 8;
    uint32_t sw = boff ^ ((boff >> 3) & 0x70);
    *(uint2*)(g_embf + chunk * 32768 + sw) = u;
}

// ---------------- KL: exact fp32 label cosine ----------------
__global__ void kl_label(const float* __restrict__ weight, const int* __restrict__ labels) {
    int n = blockIdx.x;
    int wid = threadIdx.x >> 5;   // 0..2 (subcenter)
    int lane = threadIdx.x & 31;
    int lab = labels[n];
    if (lab < 0) lab = 0;
    if (lab >= NUM_CLASSES) lab = NUM_CLASSES - 1;

    const float4* er = g_enorm4 + n * (EMBED_DIM / 4);
    const float4* wr = (const float4*)(weight + (size_t)(lab * NUM_SUB + wid) * EMBED_DIM);
    float d = 0.0f, q = 0.0f;
    #pragma unroll
    for (int j = 0; j < 4; j++) {
        float4 e = er[lane + 32 * j];
        float4 w = wr[lane + 32 * j];
        d += e.x * w.x + e.y * w.y + e.z * w.z + e.w * w.w;
        q += w.x * w.x + w.y * w.y + w.z * w.z + w.w * w.w;
    }
    #pragma unroll
    for (int o = 16; o > 0; o >>= 1) {
        d += __shfl_xor_sync(0xFFFFFFFFu, d, o);
        q += __shfl_xor_sync(0xFFFFFFFFu, q, o);
    }
    __shared__ float sc[3];
    if (lane == 0) sc[wid] = d / fmaxf(sqrtf(q), 1e-12f);
    __syncthreads();
    if (threadIdx.x == 0) g_labcos[n] = fmaxf(sc[0], fmaxf(sc[1], sc[2]));
}

// ---------------- K2: pipelined bf16 HMMA GEMM + fused epilogue ----------------
// M=256 (warp w -> samples w*32..), N=96, K chunks of 64, double-buffered A (cp.async)
// and B (register prefetch -> convert), 2 syncs/chunk, next-chunk loads overlap MMA.
__global__ void __launch_bounds__(256, 1) k2_hmma(const float* __restrict__ weight) {
    extern __shared__ char sm[];
    uint32_t sb = s2u(sm);
    int tid = threadIdx.x;
    int w = tid >> 5;
    int lane = tid & 31;
    float* rsum = (float*)(sm + SM_RS);
    size_t wbase = (size_t)blockIdx.x * NT;

    if (tid < NT) rsum[tid] = 0.0f;

    float acc[2][12][4];
    #pragma unroll
    for (int mt = 0; mt < 2; mt++)
        #pragma unroll
        for (int nt = 0; nt < 12; nt++)
            #pragma unroll
            for (int i = 0; i < 4; i++) acc[mt][nt][i] = 0.0f;

    // --- ldmatrix lane address precompute ---
    int a_r0 = w * 32 + (lane & 7) + ((lane >> 3) & 1) * 8;
    uint32_t a_hi16 = ((lane >> 4) & 1) * 16;
    uint32_t xrA = (uint32_t)((a_r0 & 7) << 4);
    uint32_t aOff = (uint32_t)a_r0 * 128;               // + buf base
    int b_r0 = (lane & 7) + ((lane >> 4) & 1) * 8;
    uint32_t b_k16 = ((lane >> 3) & 1) * 16;
    uint32_t xrB = (uint32_t)((b_r0 & 7) << 4);
    uint32_t bOff = (uint32_t)b_r0 * 128;

    // --- B prefetch mapping: flat idx = tid + 256*i over 1536 float4s ---
    // row = idx>>4 (16 float4 per row = 64 floats), f = idx&15
    float4 breg[6];
    const float4* wptr = (const float4*)(weight + wbase * EMBED_DIM);

    // prologue: B chunk 0 into regs, A chunk 0 via cp.async
    #pragma unroll
    for (int i = 0; i < 6; i++) {
        int idx = tid + 256 * i;
        breg[i] = wptr[(size_t)(idx >> 4) * 128 + (idx & 15)];   // 128 float4 per row stride
    }
    {
        const char* src = (const char*)g_embf + (size_t)tid * 16;
        uint32_t dst = sb + SM_A0 + tid * 16;
        #pragma unroll
        for (int i = 0; i < 8; i++) CP_ASYNC16(dst + i * 4096, src + i * 4096);
        CP_COMMIT();
    }

    for (int kc = 0; kc < NCHUNK; kc++) {
        int buf = kc & 1;
        uint32_t aBase = sb + (buf ? SM_A1 : SM_A0);
        uint32_t bBase = sb + (buf ? SM_B1 : SM_B0);

        CP_WAIT0();
        __syncthreads();   // A[kc] landed everywhere; MMA(kc-2) reads of these bufs done

        // convert prefetched B regs -> smem (swizzled) + sumsq
        {
            char* bdst = sm + (buf ? SM_B1 : SM_B0);
            #pragma unroll
            for (int i = 0; i < 6; i++) {
                int idx = tid + 256 * i;
                int row = idx >> 4;
                int f = idx & 15;
                float4 v = breg[i];
                float ss = v.x * v.x + v.y * v.y + v.z * v.z + v.w * v.w;
                __nv_bfloat162 p0 = __floats2bfloat162_rn(v.x, v.y);
                __nv_bfloat162 p1 = __floats2bfloat162_rn(v.z, v.w);
                uint2 u;
                u.x = *(uint32_t*)&p0;
                u.y = *(uint32_t*)&p1;
                uint32_t kb = (uint32_t)f * 8;
                *(uint2*)(bdst + row * 128 + (kb ^ ((row & 7) << 4))) = u;
                // 16-lane row reduction for sumsq
                ss += __shfl_xor_sync(0xFFFFFFFFu, ss, 1);
                ss += __shfl_xor_sync(0xFFFFFFFFu, ss, 2);
                ss += __shfl_xor_sync(0xFFFFFFFFu, ss, 4);
                ss += __shfl_xor_sync(0xFFFFFFFFu, ss, 8);
                if ((tid & 15) == 0) rsum[row] += ss;
            }
        }

        // issue next A chunk cp.async into other buffer
        if (kc < NCHUNK - 1) {
            const char* src = (const char*)g_embf + (size_t)(kc + 1) * 32768 + (size_t)tid * 16;
            uint32_t dst = sb + (buf ? SM_A0 : SM_A1) + tid * 16;
            #pragma unroll
            for (int i = 0; i < 8; i++) CP_ASYNC16(dst + i * 4096, src + i * 4096);
            CP_COMMIT();
        }
        __syncthreads();   // B[kc] smem visible

        // issue next B LDGs (complete during MMA)
        if (kc < NCHUNK - 1) {
            const float4* wp = (const float4*)(weight + wbase * EMBED_DIM + (kc + 1) * KCH);
            #pragma unroll
            for (int i = 0; i < 6; i++) {
                int idx = tid + 256 * i;
                breg[i] = wp[(size_t)(idx >> 4) * 128 + (idx & 15)];
            }
        }

        // MMA: 4 k-steps x (2 m-tiles x 12 n-tiles)
        uint32_t aRow0 = aBase + aOff;
        uint32_t aRow1 = aRow0 + 16 * 128;
        uint32_t bRow0 = bBase + bOff;
        #pragma unroll
        for (int ks = 0; ks < 4; ks++) {
            uint32_t kbA = ((uint32_t)(ks * 32) + a_hi16) ^ xrA;
            uint32_t kbB = ((uint32_t)(ks * 32) + b_k16) ^ xrB;
            uint32_t a0[4], a1[4], bfr[6][4];
            LDM_X4(a0, aRow0 + kbA);
            LDM_X4(a1, aRow1 + kbA);
            #pragma unroll
            for (int g = 0; g < 6; g++) LDM_X4(bfr[g], bRow0 + g * 2048 + kbB);
            #pragma unroll
            for (int nt = 0; nt < 12; nt++) {
                uint32_t b0 = bfr[nt >> 1][(nt & 1) * 2];
                uint32_t b1 = bfr[nt >> 1][(nt & 1) * 2 + 1];
                mma16816(acc[0][nt], a0, b0, b1);
                mma16816(acc[1][nt], a1, b0, b1);
            }
        }
    }
    __syncthreads();   // all ldmatrix reads done before cm overwrites buffers

    // finalize row rnorms
    if (tid < NT) rsum[tid] = 1.0f / fmaxf(sqrtf(rsum[tid]), 1e-12f);

    // dump accumulators to cm[256][97]
    float* cm = (float*)sm;
    int mrow = w * 32 + (lane >> 2);
    int mcol = (lane & 3) * 2;
    #pragma unroll
    for (int mt = 0; mt < 2; mt++) {
        #pragma unroll
        for (int nt = 0; nt < 12; nt++) {
            int m = mrow + mt * 16;
            int n = nt * 8 + mcol;
            cm[m * CM_STRIDE + n]           = acc[mt][nt][0];
            cm[m * CM_STRIDE + n + 1]       = acc[mt][nt][1];
            cm[(m + 8) * CM_STRIDE + n]     = acc[mt][nt][2];
            cm[(m + 8) * CM_STRIDE + n + 1] = acc[mt][nt][3];
        }
    }
    __syncthreads();

    // thread tid = sample tid: 32 classes, subcenter-max, exp-sum
    float psum = 0.0f;
    const float* myrow = cm + tid * CM_STRIDE;
    #pragma unroll 8
    for (int c = 0; c < NT / 3; c++) {
        float c0 = myrow[3 * c + 0] * rsum[3 * c + 0];
        float c1 = myrow[3 * c + 1] * rsum[3 * c + 1];
        float c2 = myrow[3 * c + 2] * rsum[3 * c + 2];
        float m = fmaxf(c0, fmaxf(c1, c2));
        psum += __expf(SCALE * m - 64.0f);
    }
    g_part[(size_t)blockIdx.x * BATCH + tid] = psum;
}

// ---------------- K3a: per-sample partial reduce (deterministic) ----------------
__global__ void k3a_reduce() {
    int n = blockIdx.x;
    int t = threadIdx.x;   // 256
    float s = 0.0f;
    for (int c = t; c < NCTA; c += 256) s += g_part[(size_t)c * BATCH + n];
    __shared__ float red[256];
    red[t] = s;
    __syncthreads();
    for (int o = 128; o > 0; o >>= 1) { if (t < o) red[t] += red[t + o]; __syncthreads(); }
    if (t == 0) g_sums[n] = red[0];
}

// ---------------- K3b: margin correction + loss + mean ----------------
__global__ void k3b_final(float* __restrict__ out) {
    int tid = threadIdx.x;   // 256
    float tot = g_sums[tid];
    float cl = g_labcos[tid];
    float sine = sqrtf(fminf(fmaxf(1.0f - cl * cl, 0.0f), 1.0f));
    float phi = cl * COS_M - sine * SIN_M;
    phi = (cl > TH_) ? phi : (cl - MM_);
    float t2 = tot - __expf(SCALE * cl - 64.0f) + __expf(SCALE * phi - 64.0f);
    float loss = 64.0f + logf(t2) - SCALE * phi;

    __shared__ float red[256];
    red[tid] = loss;
    __syncthreads();
    for (int o = 128; o > 0; o >>= 1) { if (tid < o) red[tid] += red[tid + o]; __syncthreads(); }
    if (tid == 0) out[0] = red[0] * (1.0f / BATCH);
}

// ---------------- launch ----------------
extern "C" void kernel_launch(void* const* d_in, const int* in_sizes, int n_in,
                              void* d_out, int out_size) {
    const float* emb    = (const float*)d_in[0];
    const int*   labels = (const int*)d_in[1];     // int32 (JAX x64 disabled)
    const float* weight = (const float*)d_in[2];
    float* out = (float*)d_out;

    k1_normalize<<<BATCH, 128>>>(emb);
    kl_label<<<BATCH, 96>>>(weight, labels);

    cudaFuncSetAttribute(k2_hmma, cudaFuncAttributeMaxDynamicSharedMemorySize, SMEM_REQ);
    k2_hmma<<<NCTA, 256, SMEM_REQ>>>(weight);

    k3a_reduce<<<BATCH, 256>>>();
    k3b_final<<<1, 256>>>(out);
}